// round 7
// baseline (speedup 1.0000x reference)
#include <cuda_runtime.h>
#include <cstdint>

// OrderParameter: C=30000 centrals, K=32 neighbors. One warp per central.
// Fast path (mask all-ones): symmetric-pair loop, offsets o=1..16, lane j pairs
// with (j+o) mod 32; offsets packed (o, o+8) in f32x2 through dot/acos chain.
// r-space trick: r = acos(|c|); then
//   theta > 160deg (c<0):  (theta-pi)^2   = r^2
//   any sign:              (theta-pi/2)^2 = (r-pi/2)^2
//   lt tetra center:       theta0 (c>=0) or pi-theta0 (c<0)
// One merged exp per pair serves tetra-gaussian (lt) or term1 (gt); the tetra
// gaussian for gt pairs is <= 2.8e-6 and is dropped (error ~1e-5 in G).
//
//   q_tet   = 1 - 3*S/(n(n-1))
//   q_tetra = G/(n(n-1))
//   q_oct   = [2*T1 + sum_rows e2s_j*(row_lt_j-1)] / (n*(3+(n-2)(n-3)))
//
// row_lt/e2s packed per row: val = 2.25*e2 + 256 (lt) or 0 (gt); v <= 8006,
// cnt = floor(v/256 + 0.03) exact.

#define FULLMASK 0xffffffffu

__device__ __forceinline__ float ex2f(float x) {
    float r; asm("ex2.approx.f32 %0, %1;" : "=f"(r) : "f"(x)); return r;
}
__device__ __forceinline__ float sqrt_ap(float x) {
    float r; asm("sqrt.approx.f32 %0, %1;" : "=f"(r) : "f"(x)); return r;
}

// ---- f32x2 packed helpers ----
__device__ __forceinline__ uint64_t pk2(float lo, float hi) {
    uint64_t d; asm("mov.b64 %0, {%1, %2};" : "=l"(d) : "f"(lo), "f"(hi)); return d;
}
__device__ __forceinline__ void upk2(uint64_t d, float& lo, float& hi) {
    asm("mov.b64 {%0, %1}, %2;" : "=f"(lo), "=f"(hi) : "l"(d));
}
__device__ __forceinline__ uint64_t bc2(float v) { return pk2(v, v); }
__device__ __forceinline__ uint64_t f2mul(uint64_t a, uint64_t b) {
    uint64_t d; asm("mul.rn.f32x2 %0, %1, %2;" : "=l"(d) : "l"(a), "l"(b)); return d;
}
__device__ __forceinline__ uint64_t f2add(uint64_t a, uint64_t b) {
    uint64_t d; asm("add.rn.f32x2 %0, %1, %2;" : "=l"(d) : "l"(a), "l"(b)); return d;
}
__device__ __forceinline__ uint64_t f2fma(uint64_t a, uint64_t b, uint64_t c) {
    uint64_t d; asm("fma.rn.f32x2 %0, %1, %2, %3;" : "=l"(d) : "l"(a), "l"(b), "l"(c)); return d;
}

// ---- constants ----
#define PI_F      3.14159265358979323846f
#define HALF_PI_F 1.57079632679489661923f
#define THETA0_F  1.91061193216957395f     // 109.47 deg
#define PMT0_F    1.23098072142021928f     // pi - theta0
#define THR_F     2.79252680319092716f     // 160 deg
#define COS_THR_F (-0.93969262078590838f)  // cos(160 deg)
#define LOG2E_F   1.44269504088896340f
#define D_LT_F    0.17453292519943295f     // 10 deg
#define D1_F      0.20943951023931953f     // 12 deg
#define KG_F  (-LOG2E_F / (2.0f * D_LT_F * D_LT_F))   // 10-deg widths (tetra, term2)
#define K1_F  (-LOG2E_F / (2.0f * D1_F  * D1_F ))     // term1 (12 deg)

// Scalar tail for one pair working in r-space. WH: weight for symmetric sums
// (1.0, or 0.5 for the o=16 half). Returns packed val for the row quantities.
template<int WH2>   // weight*2 as int to keep it compile-time (2 or 1)
__device__ __forceinline__ float tail_r(float r, float c, float& g, float& t1)
{
    const float wsym = 0.5f * (float)WH2;
    const bool gt = c < COS_THR_F;                  // theta > 160 deg
    // merged exp1: gt -> K1*r^2 (term1); lt -> KG*(r-ctr)^2 (tetra gaussian)
    const float ctr = gt ? 0.0f : ((c >= 0.0f) ? THETA0_F : PMT0_F);
    const float kk  = gt ? K1_F : KG_F;
    const float d1  = r - ctr;
    const float e1  = ex2f((kk * d1) * d1);
    g  = fmaf(gt ? 0.0f : wsym,        e1, g);
    t1 = fmaf(gt ? 3.0f * wsym : 0.0f, e1, t1);
    // exp2: (theta-pi/2)^2 = (r-pi/2)^2, needed for lt only
    const float d2 = r - HALF_PI_F;
    const float e2 = ex2f((KG_F * d2) * d2);
    return gt ? 0.0f : fmaf(2.25f, e2, 256.0f);
}

// One packed step: offsets (O0, O1). LAST => O1==16 (hi half-weighted for the
// symmetric sums, own-only row accumulation).
template<int O0, int O1, bool LAST>
__device__ __forceinline__ void pair_step(
    uint64_t x2, uint64_t y2, uint64_t z2,
    float x, float y, float z, int lane,
    uint64_t& s2, float& g, float& t1, float& vo, float& vm)
{
    // modulo-wrap shuffles (srcLane % 32 semantics)
    const float xl = __shfl_sync(FULLMASK, x, lane + O0);
    const float yl = __shfl_sync(FULLMASK, y, lane + O0);
    const float zl = __shfl_sync(FULLMASK, z, lane + O0);
    const float xh = __shfl_sync(FULLMASK, x, lane + O1);
    const float yh = __shfl_sync(FULLMASK, y, lane + O1);
    const float zh = __shfl_sync(FULLMASK, z, lane + O1);

    const uint64_t c2 = f2fma(x2, pk2(xl, xh),
                        f2fma(y2, pk2(yl, yh), f2mul(z2, pk2(zl, zh))));

    // q_tet: (c + 1/3)^2, hi half-weight on last step
    const uint64_t a2  = f2add(c2, bc2(1.0f / 3.0f));
    const uint64_t aa2 = f2mul(a2, a2);
    s2 = LAST ? f2fma(aa2, pk2(1.0f, 0.5f), s2) : f2add(aa2, s2);

    // packed r = acos(|c|) via A&S 4.4.46: sqrt(1-|c|)*poly(|c|)
    const uint64_t t2 = c2 & 0x7FFFFFFF7FFFFFFFull;
    uint64_t p2 = bc2(-0.0012624911f);
    p2 = f2fma(p2, t2, bc2( 0.0066700901f));
    p2 = f2fma(p2, t2, bc2(-0.0170881256f));
    p2 = f2fma(p2, t2, bc2( 0.0308918810f));
    p2 = f2fma(p2, t2, bc2(-0.0501743046f));
    p2 = f2fma(p2, t2, bc2( 0.0889789874f));
    p2 = f2fma(p2, t2, bc2(-0.2145988016f));
    p2 = f2fma(p2, t2, bc2( 1.5707963050f));
    const uint64_t om2 = f2fma(t2, bc2(-1.0f), bc2(1.0f));   // 1-|c| >= -2e-7
    float omlo, omhi; upk2(om2, omlo, omhi);
    const uint64_t sq2 = pk2(sqrt_ap(fmaxf(omlo, 0.0f)), sqrt_ap(fmaxf(omhi, 0.0f)));
    const uint64_t r2 = f2mul(sq2, p2);                      // r = acos(|c|)

    float rlo, rhi; upk2(r2, rlo, rhi);
    float clo, chi; upk2(c2, clo, chi);

    const float vlo = tail_r<2>(rlo, clo, g, t1);
    const float vhi = LAST ? tail_r<1>(rhi, chi, g, t1)
                           : tail_r<2>(rhi, chi, g, t1);

    vo += vlo + vhi;
    vm += __shfl_sync(FULLMASK, vlo, lane + (32 - O0));
    const float mh = __shfl_sync(FULLMASK, vhi, lane + (32 - O1));
    if (!LAST) vm += mh;
}

__global__ __launch_bounds__(256) void order_param_kernel(
    const float* __restrict__ vecs,  // [C, 32, 3]
    const int*   __restrict__ mask,  // [C, 32] int32 0/1
    float* __restrict__ out,         // [3, C]
    int C)
{
    const int warp_global = (blockIdx.x * blockDim.x + threadIdx.x) >> 5;
    const int lane = threadIdx.x & 31;
    if (warp_global >= C) return;

    const float* vp = vecs + (size_t)warp_global * 96 + lane * 3;
    const bool valid = mask[(size_t)warp_global * 32 + lane] != 0;
    float x = 0.0f, y = 0.0f, z = 1.0f;
    if (valid) { x = vp[0]; y = vp[1]; z = vp[2]; }
    const float inv = rsqrtf(fmaf(x, x, fmaf(y, y, z * z)));
    x *= inv; y *= inv; z *= inv;

    const unsigned mm = __ballot_sync(FULLMASK, valid);

    float S, G, O;

    if (mm == FULLMASK) {
        // ---------- fast path: all 32 neighbors valid ----------
        const uint64_t x2 = bc2(x), y2 = bc2(y), z2 = bc2(z);
        uint64_t s2 = 0;
        float g = 0.0f, t1 = 0.0f, vo = 0.0f, vm = 0.0f;

        pair_step<1, 9,  false>(x2, y2, z2, x, y, z, lane, s2, g, t1, vo, vm);
        pair_step<2, 10, false>(x2, y2, z2, x, y, z, lane, s2, g, t1, vo, vm);
        pair_step<3, 11, false>(x2, y2, z2, x, y, z, lane, s2, g, t1, vo, vm);
        pair_step<4, 12, false>(x2, y2, z2, x, y, z, lane, s2, g, t1, vo, vm);
        pair_step<5, 13, false>(x2, y2, z2, x, y, z, lane, s2, g, t1, vo, vm);
        pair_step<6, 14, false>(x2, y2, z2, x, y, z, lane, s2, g, t1, vo, vm);
        pair_step<7, 15, false>(x2, y2, z2, x, y, z, lane, s2, g, t1, vo, vm);
        pair_step<8, 16, true >(x2, y2, z2, x, y, z, lane, s2, g, t1, vo, vm);

        float slo, shi; upk2(s2, slo, shi);
        S = 2.0f * (slo + shi);
        G = 2.0f * g;
        const float v   = vo + vm;                          // e2s + 256*row_lt
        const float cnt = floorf(fmaf(v, 1.0f / 256.0f, 0.03f));
        const float e2s = fmaf(-256.0f, cnt, v);
        O = fmaf(e2s, cnt - 1.0f, 2.0f * t1);
    } else {
        // ---------- generic path (verified R3 loop) ----------
        const float NEG_I2DLT2 = -1.0f / (2.0f * D_LT_F * D_LT_F);
        const float NEG_I2D12  = -1.0f / (2.0f * D1_F * D1_F);

        float s_acc = 0.0f, g_acc = 0.0f, t1_acc = 0.0f, e2s = 0.0f;
        int row_lt = 0;
        #pragma unroll
        for (int o = 1; o <= 16; o++) {
            const int p = (lane + o) & 31;
            const float vx = __shfl_sync(FULLMASK, x, p);
            const float vy = __shfl_sync(FULLMASK, y, p);
            const float vz = __shfl_sync(FULLMASK, z, p);
            const bool pv = valid && ((mm >> p) & 1u);
            const float w = pv ? 1.0f : 0.0f;

            float c = fmaf(x, vx, fmaf(y, vy, z * vz));
            c = fminf(1.0f, fmaxf(-1.0f, c));
            const float th = acosf(c);

            const float a = c + (1.0f / 3.0f);
            const float s_p = w * a * a;
            const float d0 = th - THETA0_F;
            const float g_p = w * __expf(d0 * d0 * NEG_I2DLT2);
            const float dpi = th - PI_F;
            const float t1_p = (th > THR_F) ? (3.0f * w * __expf(dpi * dpi * NEG_I2D12)) : 0.0f;
            const bool lt = pv && (th < THR_F);
            const float dh = th - HALF_PI_F;
            const float e2_p = lt ? (2.25f * __expf(dh * dh * NEG_I2DLT2)) : 0.0f;
            const unsigned ltm = __ballot_sync(FULLMASK, lt);

            if (o < 16) {
                s_acc += s_p; g_acc += g_p; t1_acc += t1_p;
                const int q = (lane - o) & 31;
                e2s += e2_p + __shfl_sync(FULLMASK, e2_p, q);
                row_lt += (int)((ltm >> lane) & 1u) + (int)((ltm >> q) & 1u);
            } else {
                s_acc  = fmaf(0.5f, s_p,  s_acc);
                g_acc  = fmaf(0.5f, g_p,  g_acc);
                t1_acc = fmaf(0.5f, t1_p, t1_acc);
                e2s += e2_p;
                row_lt += (int)((ltm >> lane) & 1u);
            }
        }
        S = 2.0f * s_acc;
        G = 2.0f * g_acc;
        O = fmaf(e2s, (float)(row_lt - 1), 2.0f * t1_acc);
    }

    #pragma unroll
    for (int off = 16; off > 0; off >>= 1) {
        S += __shfl_xor_sync(FULLMASK, S, off);
        G += __shfl_xor_sync(FULLMASK, G, off);
        O += __shfl_xor_sync(FULLMASK, O, off);
    }

    if (lane == 0) {
        const float n   = (float)__popc(mm);
        const float nn1 = n * (n - 1.0f);
        out[warp_global]         = 1.0f - 3.0f * S / nn1;
        out[C + warp_global]     = G / nn1;
        out[2 * C + warp_global] = O / (n * (3.0f + (n - 2.0f) * (n - 3.0f)));
    }
}

extern "C" void kernel_launch(void* const* d_in, const int* in_sizes, int n_in,
                              void* d_out, int out_size) {
    const float* vecs = (const float*)d_in[0];
    const int*   mask = (const int*)d_in[1];
    float* out = (float*)d_out;
    const int C = in_sizes[0] / (32 * 3);

    const int warps_per_block = 8;   // 256 threads
    const int blocks = (C + warps_per_block - 1) / warps_per_block;
    order_param_kernel<<<blocks, 256>>>(vecs, mask, out, C);
}